// round 10
// baseline (speedup 1.0000x reference)
#include <cuda_runtime.h>
#include <cuda_bf16.h>

// Problem shape (fixed by dataset)
#define NMAX 50000
#define EMAX 600000
#define DIM  128
#define GR   32        // rows per block in QKV GEMM
#define SCAN_TILE 2048 // elems per scan block (256 thr x 8)
#define SCAN_MAXB 64   // max scan blocks (50000/2048 -> 25)

// ---------------- device scratch (static allocation only) ----------------
__device__ float g_Q[NMAX * DIM];
__device__ float g_K[NMAX * DIM];
__device__ float g_V[NMAX * DIM];
__device__ int   g_deg[NMAX + 8];      // zero-init at load; re-zeroed by scan_p3 each call
__device__ int   g_rowptr[NMAX + 1];
__device__ int   g_cursor[NMAX];
__device__ int   g_ecol[EMAX];         // cols permuted into CSR order
__device__ int   g_bsum[SCAN_MAXB];
__device__ int   g_boff[SCAN_MAXB];

// ---------------- packed f32x2 helpers ----------------
__device__ __forceinline__ void ffma2(unsigned long long& acc,
                                      unsigned long long a,
                                      unsigned long long b) {
    asm("fma.rn.f32x2 %0, %1, %2, %0;" : "+l"(acc) : "l"(a), "l"(b));
}
__device__ __forceinline__ unsigned long long bcast2(float x) {
    unsigned long long r;
    unsigned u = __float_as_uint(x);
    asm("mov.b64 %0, {%1, %1};" : "=l"(r) : "r"(u));
    return r;
}
__device__ __forceinline__ void unpack2(unsigned long long v, float& lo, float& hi) {
    unsigned a, b;
    asm("mov.b64 {%0, %1}, %2;" : "=r"(a), "=r"(b) : "l"(v));
    lo = __uint_as_float(a);
    hi = __uint_as_float(b);
}

// ---------------- kernel 1: fused Q/K/V projection (packed f32x2, GR=32) ----------------
__global__ void __launch_bounds__(128) qkv_kernel(
    const float* __restrict__ emb,
    const float* __restrict__ wq,
    const float* __restrict__ wk,
    const float* __restrict__ wv,
    int n)
{
    __shared__ __align__(16) float et[DIM][36];   // 144B stride: 16B aligned, bank spread
    const int j  = threadIdx.x;                   // output column 0..127
    const int r0 = blockIdx.x * GR;

    #pragma unroll
    for (int r = 0; r < GR; r++) {
        int row = r0 + r;
        et[j][r] = (row < n) ? emb[row * DIM + j] : 0.f;
    }
    __syncthreads();

    unsigned long long aq[16], ak[16], av[16];
    #pragma unroll
    for (int i = 0; i < 16; i++) { aq[i] = 0ull; ak[i] = 0ull; av[i] = 0ull; }

    #pragma unroll 2
    for (int k = 0; k < DIM; k++) {
        unsigned long long q2 = bcast2(__ldg(&wq[k * DIM + j]));
        unsigned long long k2 = bcast2(__ldg(&wk[k * DIM + j]));
        unsigned long long v2 = bcast2(__ldg(&wv[k * DIM + j]));
        const ulonglong2* ep = (const ulonglong2*)(&et[k][0]);
        #pragma unroll
        for (int p = 0; p < 8; p++) {
            ulonglong2 e2 = ep[p];
            ffma2(aq[2 * p],     e2.x, q2);
            ffma2(aq[2 * p + 1], e2.y, q2);
            ffma2(ak[2 * p],     e2.x, k2);
            ffma2(ak[2 * p + 1], e2.y, k2);
            ffma2(av[2 * p],     e2.x, v2);
            ffma2(av[2 * p + 1], e2.y, v2);
        }
    }

    #pragma unroll
    for (int i = 0; i < 16; i++) {
        float qlo, qhi, klo, khi, vlo, vhi;
        unpack2(aq[i], qlo, qhi);
        unpack2(ak[i], klo, khi);
        unpack2(av[i], vlo, vhi);
        int row = r0 + 2 * i;
        if (row < n) {
            g_Q[row * DIM + j] = qlo;
            g_K[row * DIM + j] = klo;
            g_V[row * DIM + j] = vlo;
        }
        if (row + 1 < n) {
            g_Q[(row + 1) * DIM + j] = qhi;
            g_K[(row + 1) * DIM + j] = khi;
            g_V[(row + 1) * DIM + j] = vhi;
        }
    }
}

// ---------------- kernel 2: degree histogram ----------------
__global__ void hist_kernel(const int* __restrict__ rows, int E) {
    int i = blockIdx.x * blockDim.x + threadIdx.x;
    if (i < E) atomicAdd(&g_deg[rows[i]], 1);
}

// ---------------- scan phase 1: per-block sums ----------------
__global__ void __launch_bounds__(256) scan_p1_kernel(int n) {
    __shared__ int ws[8];
    const int tid  = threadIdx.x;
    const int lane = tid & 31;
    const int wid  = tid >> 5;
    int base = blockIdx.x * SCAN_TILE + tid * 8;

    const int4* d4 = (const int4*)&g_deg[base];
    int s = 0;
    if (base < n) {
        int4 a = d4[0], b = d4[1];
        s = a.x + a.y + a.z + a.w + b.x + b.y + b.z + b.w;  // pad is zero
    }
    #pragma unroll
    for (int off = 16; off; off >>= 1) s += __shfl_xor_sync(0xffffffffu, s, off);
    if (lane == 0) ws[wid] = s;
    __syncthreads();
    if (tid == 0) {
        int t = 0;
        #pragma unroll
        for (int w = 0; w < 8; w++) t += ws[w];
        g_bsum[blockIdx.x] = t;
    }
}

// ---------------- scan phase 2: scan block sums (1 warp) ----------------
__global__ void scan_p2_kernel(int nblocks, int n) {
    int lane = threadIdx.x;
    __shared__ int carry;
    if (lane == 0) carry = 0;
    __syncwarp();
    for (int b0 = 0; b0 < nblocks; b0 += 32) {
        int i = b0 + lane;
        int v = (i < nblocks) ? g_bsum[i] : 0;
        int inc = v;
        #pragma unroll
        for (int off = 1; off < 32; off <<= 1) {
            int t = __shfl_up_sync(0xffffffffu, inc, off);
            if (lane >= off) inc += t;
        }
        int c = carry;
        if (i < nblocks) g_boff[i] = c + inc - v;
        if (lane == 31) carry = c + inc;
        __syncwarp();
    }
    if (lane == 0) g_rowptr[n] = carry;   // grand total
}

// ---------------- scan phase 3: rescan tiles, then re-zero deg for next call ----------------
__global__ void __launch_bounds__(256) scan_p3_kernel(int n) {
    __shared__ int warp_off[8];
    const int tid  = threadIdx.x;
    const int lane = tid & 31;
    const int wid  = tid >> 5;
    int base = blockIdx.x * SCAN_TILE + tid * 8;

    int v[8];
    int tot = 0;
    if (base < n) {
        int4* d4 = (int4*)&g_deg[base];
        int4 a = d4[0], b = d4[1];
        int d[8] = {a.x, a.y, a.z, a.w, b.x, b.y, b.z, b.w};
        #pragma unroll
        for (int i = 0; i < 8; i++) { v[i] = tot; tot += d[i]; }
        // leave deg zeroed so next graph replay's hist starts clean (replaces zero kernel)
        d4[0] = make_int4(0, 0, 0, 0);
        d4[1] = make_int4(0, 0, 0, 0);
    } else {
        #pragma unroll
        for (int i = 0; i < 8; i++) v[i] = 0;
    }

    int inc = tot;
    #pragma unroll
    for (int off = 1; off < 32; off <<= 1) {
        int t = __shfl_up_sync(0xffffffffu, inc, off);
        if (lane >= off) inc += t;
    }
    if (lane == 31) warp_off[wid] = inc;
    int texcl = inc - tot;
    __syncthreads();

    if (wid == 0 && lane < 8) {
        int w = warp_off[lane];
        int wi = w;
        #pragma unroll
        for (int off = 1; off < 8; off <<= 1) {
            int t = __shfl_up_sync(0x000000ffu, wi, off);
            if (lane >= off) wi += t;
        }
        warp_off[lane] = wi - w;
    }
    __syncthreads();

    int b = g_boff[blockIdx.x] + warp_off[wid] + texcl;
    #pragma unroll
    for (int i = 0; i < 8; i++) {
        int idx = base + i;
        if (idx < n) {
            int val = b + v[i];
            g_rowptr[idx] = val;
            g_cursor[idx] = val;
        }
    }
}

// ---------------- kernel 4: scatter col ids into CSR order ----------------
__global__ void scatter_kernel(const int* __restrict__ rows,
                               const int* __restrict__ cols, int E) {
    int i = blockIdx.x * blockDim.x + threadIdx.x;
    if (i < E) {
        int pos = atomicAdd(&g_cursor[rows[i]], 1);
        g_ecol[pos] = cols[i];
    }
}

// ---------------- kernel 5: fused single-pass attention, 4-edge unrolled ----------------
// One warp per destination node. Lane l holds dims [4l, 4l+4); head = l>>3.
// out = (sum_e ea_e * v_e) / (sum_e ea_e + 1e-8)
__device__ __forceinline__ float hdot(float4 q, float4 k) {
    return fmaf(q.x, k.x, fmaf(q.y, k.y, fmaf(q.z, k.z, q.w * k.w)));
}
__device__ __forceinline__ float hred(float p) {   // reduce over 8-lane head group
    p += __shfl_xor_sync(0xffffffffu, p, 1);
    p += __shfl_xor_sync(0xffffffffu, p, 2);
    p += __shfl_xor_sync(0xffffffffu, p, 4);
    return p;
}
__device__ __forceinline__ float eclip(float p) {
    return __expf(fminf(fmaxf(p, -10.f), 10.f));
}

__global__ void __launch_bounds__(256) attn_kernel(float* __restrict__ out, int n)
{
    int gw   = (blockIdx.x * blockDim.x + threadIdx.x) >> 5;
    int lane = threadIdx.x & 31;
    if (gw >= n) return;

    const float4* Q4 = (const float4*)g_Q;
    const float4* K4 = (const float4*)g_K;
    const float4* V4 = (const float4*)g_V;

    float4 qv = Q4[gw * 32 + lane];
    int beg = g_rowptr[gw];
    int end = g_rowptr[gw + 1];

    float nsum = 0.f;
    float4 acc = make_float4(0.f, 0.f, 0.f, 0.f);

    int idx = beg;
    for (; idx + 4 <= end; idx += 4) {
        int c0 = g_ecol[idx];
        int c1 = g_ecol[idx + 1];
        int c2 = g_ecol[idx + 2];
        int c3 = g_ecol[idx + 3];
        // 8 independent gathers in flight
        float4 k0 = K4[c0 * 32 + lane];
        float4 k1 = K4[c1 * 32 + lane];
        float4 k2 = K4[c2 * 32 + lane];
        float4 k3 = K4[c3 * 32 + lane];
        float4 v0 = V4[c0 * 32 + lane];
        float4 v1 = V4[c1 * 32 + lane];
        float4 v2 = V4[c2 * 32 + lane];
        float4 v3 = V4[c3 * 32 + lane];
        float p0 = hdot(qv, k0), p1 = hdot(qv, k1), p2 = hdot(qv, k2), p3 = hdot(qv, k3);
        // 4 independent shuffle-reduction chains (latency overlap)
        p0 = hred(p0); p1 = hred(p1); p2 = hred(p2); p3 = hred(p3);
        float e0 = eclip(p0), e1 = eclip(p1), e2 = eclip(p2), e3 = eclip(p3);
        nsum += (e0 + e1) + (e2 + e3);
        acc.x = fmaf(e0, v0.x, fmaf(e1, v1.x, fmaf(e2, v2.x, fmaf(e3, v3.x, acc.x))));
        acc.y = fmaf(e0, v0.y, fmaf(e1, v1.y, fmaf(e2, v2.y, fmaf(e3, v3.y, acc.y))));
        acc.z = fmaf(e0, v0.z, fmaf(e1, v1.z, fmaf(e2, v2.z, fmaf(e3, v3.z, acc.z))));
        acc.w = fmaf(e0, v0.w, fmaf(e1, v1.w, fmaf(e2, v2.w, fmaf(e3, v3.w, acc.w))));
    }
    for (; idx < end; idx++) {
        int c = g_ecol[idx];
        float4 kv = K4[c * 32 + lane];
        float4 vv = V4[c * 32 + lane];
        float ea = eclip(hred(hdot(qv, kv)));
        nsum += ea;
        acc.x = fmaf(ea, vv.x, acc.x);
        acc.y = fmaf(ea, vv.y, acc.y);
        acc.z = fmaf(ea, vv.z, acc.z);
        acc.w = fmaf(ea, vv.w, acc.w);
    }
    float inv = 1.f / (nsum + 1e-8f);
    acc.x *= inv; acc.y *= inv; acc.z *= inv; acc.w *= inv;
    ((float4*)out)[gw * 32 + lane] = acc;
}

// ---------------- launch ----------------
// Order chosen so the profiled launch (index 3) is qkv_kernel.
extern "C" void kernel_launch(void* const* d_in, const int* in_sizes, int n_in,
                              void* d_out, int out_size) {
    const float* emb  = (const float*)d_in[0];
    const float* qW   = (const float*)d_in[1];
    const float* kW   = (const float*)d_in[2];
    const float* vW   = (const float*)d_in[3];
    const int*   rows = (const int*)d_in[4];
    const int*   cols = (const int*)d_in[5];
    float*       out  = (float*)d_out;

    const int N = in_sizes[0] / DIM;   // 50000
    const int E = in_sizes[4];         // 600000
    const int nsb = (N + SCAN_TILE - 1) / SCAN_TILE;   // 25

    hist_kernel<<<(E + 255) / 256, 256>>>(rows, E);        // 0
    scan_p1_kernel<<<nsb, 256>>>(N);                       // 1
    scan_p2_kernel<<<1, 32>>>(nsb, N);                     // 2
    qkv_kernel<<<(N + GR - 1) / GR, 128>>>(emb, qW, kW, vW, N);  // 3  <- profiled
    scan_p3_kernel<<<nsb, 256>>>(N);                       // 4
    scatter_kernel<<<(E + 255) / 256, 256>>>(rows, cols, E);     // 5
    attn_kernel<<<(N + 7) / 8, 256>>>(out, N);             // 6
}

// round 11
// speedup vs baseline: 1.4173x; 1.4173x over previous
#include <cuda_runtime.h>
#include <cuda_bf16.h>

// Problem shape (fixed by dataset)
#define NMAX 50000
#define EMAX 600000
#define DIM  128
#define GR   16        // rows per block in QKV GEMM (split 8+8 across thread halves)
#define SCAN_TILE 2048 // elems per scan block (256 thr x 8)
#define SCAN_MAXB 64   // max scan blocks (50000/2048 -> 25)

// ---------------- device scratch (static allocation only) ----------------
__device__ float g_Q[NMAX * DIM];
__device__ float g_K[NMAX * DIM];
__device__ float g_V[NMAX * DIM];
__device__ int   g_deg[NMAX + 8];      // zero-init at load; re-zeroed by scan_p3 each call
__device__ int   g_rowptr[NMAX + 1];
__device__ int   g_cursor[NMAX];
__device__ int   g_ecol[EMAX];         // cols permuted into CSR order
__device__ int   g_bsum[SCAN_MAXB];
__device__ int   g_boff[SCAN_MAXB];

// ---------------- packed f32x2 helpers ----------------
__device__ __forceinline__ void ffma2(unsigned long long& acc,
                                      unsigned long long a,
                                      unsigned long long b) {
    asm("fma.rn.f32x2 %0, %1, %2, %0;" : "+l"(acc) : "l"(a), "l"(b));
}
__device__ __forceinline__ unsigned long long bcast2(float x) {
    unsigned long long r;
    unsigned u = __float_as_uint(x);
    asm("mov.b64 %0, {%1, %1};" : "=l"(r) : "r"(u));
    return r;
}
__device__ __forceinline__ void unpack2(unsigned long long v, float& lo, float& hi) {
    unsigned a, b;
    asm("mov.b64 {%0, %1}, %2;" : "=r"(a), "=r"(b) : "l"(v));
    lo = __uint_as_float(a);
    hi = __uint_as_float(b);
}

// ---------------- kernel 1: fused Q/K/V projection ----------------
// 256 threads: j = tid&127 (output column), half = tid>>7 owns 8 of the 16 rows.
// Only 12 packed accumulators per thread -> ~64 regs -> 4 blocks/SM occupancy.
__global__ void __launch_bounds__(256) qkv_kernel(
    const float* __restrict__ emb,
    const float* __restrict__ wq,
    const float* __restrict__ wk,
    const float* __restrict__ wv,
    int n)
{
    __shared__ __align__(16) float et[DIM][20];   // 80B row stride: 16B aligned, bank spread
    const int j    = threadIdx.x & 127;           // output column 0..127
    const int half = threadIdx.x >> 7;            // 0 or 1
    const int rb   = half * 8;                    // first row of this half within tile
    const int r0   = blockIdx.x * GR;

    // load: thread loads its half's 8 rows for column j (k-major tile)
    #pragma unroll
    for (int r = 0; r < 8; r++) {
        int row = r0 + rb + r;
        et[j][rb + r] = (row < n) ? emb[row * DIM + j] : 0.f;
    }
    __syncthreads();

    // 4 packed accumulators per matrix: pair i = rows (rb+2i, rb+2i+1)
    unsigned long long aq[4], ak[4], av[4];
    #pragma unroll
    for (int i = 0; i < 4; i++) { aq[i] = 0ull; ak[i] = 0ull; av[i] = 0ull; }

    #pragma unroll 4
    for (int k = 0; k < DIM; k++) {
        unsigned long long q2 = bcast2(__ldg(&wq[k * DIM + j]));
        unsigned long long k2 = bcast2(__ldg(&wk[k * DIM + j]));
        unsigned long long v2 = bcast2(__ldg(&wv[k * DIM + j]));
        const ulonglong2* ep = (const ulonglong2*)(&et[k][rb]);  // 16B aligned (80k+32h)
        #pragma unroll
        for (int p = 0; p < 2; p++) {
            ulonglong2 e2 = ep[p];    // 4 rows packed pairwise; warp-broadcast read
            ffma2(aq[2 * p],     e2.x, q2);
            ffma2(aq[2 * p + 1], e2.y, q2);
            ffma2(ak[2 * p],     e2.x, k2);
            ffma2(ak[2 * p + 1], e2.y, k2);
            ffma2(av[2 * p],     e2.x, v2);
            ffma2(av[2 * p + 1], e2.y, v2);
        }
    }

    #pragma unroll
    for (int i = 0; i < 4; i++) {
        float qlo, qhi, klo, khi, vlo, vhi;
        unpack2(aq[i], qlo, qhi);
        unpack2(ak[i], klo, khi);
        unpack2(av[i], vlo, vhi);
        int row = r0 + rb + 2 * i;
        if (row < n) {
            g_Q[row * DIM + j] = qlo;
            g_K[row * DIM + j] = klo;
            g_V[row * DIM + j] = vlo;
        }
        if (row + 1 < n) {
            g_Q[(row + 1) * DIM + j] = qhi;
            g_K[(row + 1) * DIM + j] = khi;
            g_V[(row + 1) * DIM + j] = vhi;
        }
    }
}

// ---------------- kernel 2: degree histogram ----------------
__global__ void hist_kernel(const int* __restrict__ rows, int E) {
    int i = blockIdx.x * blockDim.x + threadIdx.x;
    if (i < E) atomicAdd(&g_deg[rows[i]], 1);
}

// ---------------- scan phase 1: per-block sums ----------------
__global__ void __launch_bounds__(256) scan_p1_kernel(int n) {
    __shared__ int ws[8];
    const int tid  = threadIdx.x;
    const int lane = tid & 31;
    const int wid  = tid >> 5;
    int base = blockIdx.x * SCAN_TILE + tid * 8;

    const int4* d4 = (const int4*)&g_deg[base];
    int s = 0;
    if (base < n) {
        int4 a = d4[0], b = d4[1];
        s = a.x + a.y + a.z + a.w + b.x + b.y + b.z + b.w;  // pad is zero
    }
    #pragma unroll
    for (int off = 16; off; off >>= 1) s += __shfl_xor_sync(0xffffffffu, s, off);
    if (lane == 0) ws[wid] = s;
    __syncthreads();
    if (tid == 0) {
        int t = 0;
        #pragma unroll
        for (int w = 0; w < 8; w++) t += ws[w];
        g_bsum[blockIdx.x] = t;
    }
}

// ---------------- scan phase 2: scan block sums (1 warp) ----------------
__global__ void scan_p2_kernel(int nblocks, int n) {
    int lane = threadIdx.x;
    __shared__ int carry;
    if (lane == 0) carry = 0;
    __syncwarp();
    for (int b0 = 0; b0 < nblocks; b0 += 32) {
        int i = b0 + lane;
        int v = (i < nblocks) ? g_bsum[i] : 0;
        int inc = v;
        #pragma unroll
        for (int off = 1; off < 32; off <<= 1) {
            int t = __shfl_up_sync(0xffffffffu, inc, off);
            if (lane >= off) inc += t;
        }
        int c = carry;
        if (i < nblocks) g_boff[i] = c + inc - v;
        if (lane == 31) carry = c + inc;
        __syncwarp();
    }
    if (lane == 0) g_rowptr[n] = carry;   // grand total
}

// ---------------- scan phase 3: rescan tiles, then re-zero deg for next call ----------------
__global__ void __launch_bounds__(256) scan_p3_kernel(int n) {
    __shared__ int warp_off[8];
    const int tid  = threadIdx.x;
    const int lane = tid & 31;
    const int wid  = tid >> 5;
    int base = blockIdx.x * SCAN_TILE + tid * 8;

    int v[8];
    int tot = 0;
    if (base < n) {
        int4* d4 = (int4*)&g_deg[base];
        int4 a = d4[0], b = d4[1];
        int d[8] = {a.x, a.y, a.z, a.w, b.x, b.y, b.z, b.w};
        #pragma unroll
        for (int i = 0; i < 8; i++) { v[i] = tot; tot += d[i]; }
        // leave deg zeroed so next graph replay's hist starts clean
        d4[0] = make_int4(0, 0, 0, 0);
        d4[1] = make_int4(0, 0, 0, 0);
    } else {
        #pragma unroll
        for (int i = 0; i < 8; i++) v[i] = 0;
    }

    int inc = tot;
    #pragma unroll
    for (int off = 1; off < 32; off <<= 1) {
        int t = __shfl_up_sync(0xffffffffu, inc, off);
        if (lane >= off) inc += t;
    }
    if (lane == 31) warp_off[wid] = inc;
    int texcl = inc - tot;
    __syncthreads();

    if (wid == 0 && lane < 8) {
        int w = warp_off[lane];
        int wi = w;
        #pragma unroll
        for (int off = 1; off < 8; off <<= 1) {
            int t = __shfl_up_sync(0x000000ffu, wi, off);
            if (lane >= off) wi += t;
        }
        warp_off[lane] = wi - w;
    }
    __syncthreads();

    int b = g_boff[blockIdx.x] + warp_off[wid] + texcl;
    #pragma unroll
    for (int i = 0; i < 8; i++) {
        int idx = base + i;
        if (idx < n) {
            int val = b + v[i];
            g_rowptr[idx] = val;
            g_cursor[idx] = val;
        }
    }
}

// ---------------- kernel 4: scatter col ids into CSR order ----------------
__global__ void scatter_kernel(const int* __restrict__ rows,
                               const int* __restrict__ cols, int E) {
    int i = blockIdx.x * blockDim.x + threadIdx.x;
    if (i < E) {
        int pos = atomicAdd(&g_cursor[rows[i]], 1);
        g_ecol[pos] = cols[i];
    }
}

// ---------------- kernel 5: fused single-pass segment-softmax attention ----------------
// One warp per destination node. Lane l holds dims [4l, 4l+4); head = l>>3.
// out = (sum_e ea_e * v_e) / (sum_e ea_e + 1e-8)  — norm factored out of the sum.
__global__ void __launch_bounds__(256) attn_kernel(float* __restrict__ out, int n)
{
    int gw   = (blockIdx.x * blockDim.x + threadIdx.x) >> 5;
    int lane = threadIdx.x & 31;
    if (gw >= n) return;

    const float4* Q4 = (const float4*)g_Q;
    const float4* K4 = (const float4*)g_K;
    const float4* V4 = (const float4*)g_V;

    float4 qv = Q4[gw * 32 + lane];
    int beg = g_rowptr[gw];
    int end = g_rowptr[gw + 1];

    float nsum = 0.f;
    float4 acc = make_float4(0.f, 0.f, 0.f, 0.f);
    for (int idx = beg; idx < end; idx++) {
        int c = g_ecol[idx];                      // sequential read, CSR order
        float4 kv = K4[c * 32 + lane];            // two independent row gathers:
        float4 vv = V4[c * 32 + lane];            // issue both before the dot
        float p = fmaf(qv.x, kv.x, fmaf(qv.y, kv.y, fmaf(qv.z, kv.z, qv.w * kv.w)));
        p += __shfl_xor_sync(0xffffffffu, p, 1);
        p += __shfl_xor_sync(0xffffffffu, p, 2);
        p += __shfl_xor_sync(0xffffffffu, p, 4);  // full head dot in all 8 lanes of group
        float a  = fminf(fmaxf(p, -10.f), 10.f);
        float ea = __expf(a);
        nsum += ea;
        acc.x = fmaf(ea, vv.x, acc.x);
        acc.y = fmaf(ea, vv.y, acc.y);
        acc.z = fmaf(ea, vv.z, acc.z);
        acc.w = fmaf(ea, vv.w, acc.w);
    }
    float inv = 1.f / (nsum + 1e-8f);
    acc.x *= inv; acc.y *= inv; acc.z *= inv; acc.w *= inv;
    ((float4*)out)[gw * 32 + lane] = acc;
}

// ---------------- launch ----------------
// Order chosen so the profiled launch (index 3) is qkv_kernel.
extern "C" void kernel_launch(void* const* d_in, const int* in_sizes, int n_in,
                              void* d_out, int out_size) {
    const float* emb  = (const float*)d_in[0];
    const float* qW   = (const float*)d_in[1];
    const float* kW   = (const float*)d_in[2];
    const float* vW   = (const float*)d_in[3];
    const int*   rows = (const int*)d_in[4];
    const int*   cols = (const int*)d_in[5];
    float*       out  = (float*)d_out;

    const int N = in_sizes[0] / DIM;   // 50000
    const int E = in_sizes[4];         // 600000
    const int nsb = (N + SCAN_TILE - 1) / SCAN_TILE;   // 25

    hist_kernel<<<(E + 255) / 256, 256>>>(rows, E);        // 0
    scan_p1_kernel<<<nsb, 256>>>(N);                       // 1
    scan_p2_kernel<<<1, 32>>>(nsb, N);                     // 2
    qkv_kernel<<<(N + GR - 1) / GR, 256>>>(emb, qW, kW, vW, N);  // 3  <- profiled
    scan_p3_kernel<<<nsb, 256>>>(N);                       // 4
    scatter_kernel<<<(E + 255) / 256, 256>>>(rows, cols, E);     // 5
    attn_kernel<<<(N + 7) / 8, 256>>>(out, N);             // 6
}